// round 15
// baseline (speedup 1.0000x reference)
#include <cuda_runtime.h>

// Problem constants
#define S    256   // n_symm = 16 x 16 torus
#define NI   32    // in_features
#define NF   64    // features
#define NB   16    // batch

__constant__ float CW16[16] = {
    1.0f,  0.9238795325112867f,  0.7071067811865476f,  0.3826834323650898f,
    0.0f, -0.3826834323650898f, -0.7071067811865476f, -0.9238795325112867f,
   -1.0f, -0.9238795325112867f, -0.7071067811865476f, -0.3826834323650898f,
    0.0f,  0.3826834323650898f,  0.7071067811865476f,  0.9238795325112867f
};
__constant__ float SW16[16] = {
    0.0f,  0.3826834323650898f,  0.7071067811865476f,  0.9238795325112867f,
    1.0f,  0.9238795325112867f,  0.7071067811865476f,  0.3826834323650898f,
    0.0f, -0.3826834323650898f, -0.7071067811865476f, -0.9238795325112867f,
   -1.0f, -0.9238795325112867f, -0.7071067811865476f, -0.3826834323650898f
};

__device__ __align__(16) float2 g_xhat[S * NB * NI];   // [omega][b*32+i]
__device__ __align__(16) float2 g_khat[S * NF * NI];   // [omega][f*32+i]
__device__ __align__(16) float2 g_ohat[S * NB * NF];   // [omega][b*64+f]

__device__ __forceinline__ int conj_om(int om) {
    int u = om >> 4, w = om & 15;
    return (((16 - u) & 15) << 4) | ((16 - w) & 15);
}

// ---------------------------------------------------------------------------
// Kernel 1: forward 2D FFT (16x16), 2-for-1 real packed, radix-4,
// transposed pass-1 output (pass-2 reads rows via LDS.128). Grid 1280.
// ---------------------------------------------------------------------------
__global__ __launch_bounds__(256)
void fft_fwd_all(const float* __restrict__ x, const float* __restrict__ kern)
{
    const int pb = blockIdx.x;
    const float* in; float2* outh; int ostride, t0;
    if (pb < (NB * NI) / 2) {
        in = x;    outh = g_xhat; ostride = NB * NI; t0 = pb * 2;
    } else {
        in = kern; outh = g_khat; ostride = NF * NI;
        t0 = (pb - (NB * NI) / 2) * 2;
    }

    __shared__ float  sr[512];             // tile0 (re), tile1 (im)
    __shared__ float2 sBt[16];
    __shared__ float2 stT[16 * 18];        // pass-1 result, TRANSPOSED [w][u]
    __shared__ float2 zz[256];             // pass-2 result (for unpack)

    const int tid = threadIdx.x;
    const int u   = tid >> 4;
    const int w   = tid & 15;

    if (tid < 16) sBt[tid] = make_float2(CW16[tid], SW16[tid]);
    ((float2*)sr)[tid] = ((const float2*)(in + t0 * 256))[tid];
    __syncthreads();

    // forward twiddles: t_k = (c, -s); j = (-i)^k
    const float2 j1w = sBt[(4 * w) & 15];
    const float2 t1w = sBt[w], t2w = sBt[(2 * w) & 15], t3w = sBt[(3 * w) & 15];
    const float  ew  = 1.f - 2.f * (float)(w & 1);
    const float  jrw = j1w.x, jiw = -j1w.y;

    const float2 j1u = sBt[(4 * u) & 15];
    const float2 t1u = sBt[u], t2u = sBt[(2 * u) & 15], t3u = sBt[(3 * u) & 15];
    const float  eu  = 1.f - 2.f * (float)(u & 1);
    const float  jru = j1u.x, jiu = -j1u.y;

    // pass 1: z[v] = (tile0[u][v], tile1[u][v]); write transposed
    {
        float zr[16], zi[16];
        const float4* r4 = (const float4*)(sr + u * 16);
        const float4* i4 = (const float4*)(sr + 256 + u * 16);
        #pragma unroll
        for (int q = 0; q < 4; q++) {
            float4 a = r4[q], b = i4[q];
            zr[q*4+0]=a.x; zr[q*4+1]=a.y; zr[q*4+2]=a.z; zr[q*4+3]=a.w;
            zi[q*4+0]=b.x; zi[q*4+1]=b.y; zi[q*4+2]=b.z; zi[q*4+3]=b.w;
        }
        float Sx[4], Sy[4];
        #pragma unroll
        for (int r = 0; r < 4; r++) {
            float Px = fmaf(ew, zr[r + 8],  zr[r]);
            float Py = fmaf(ew, zi[r + 8],  zi[r]);
            float Qx = fmaf(ew, zr[r + 12], zr[r + 4]);
            float Qy = fmaf(ew, zi[r + 12], zi[r + 4]);
            Sx[r] = fmaf(jrw, Qx, fmaf(-jiw, Qy, Px));
            Sy[r] = fmaf(jrw, Qy, fmaf( jiw, Qx, Py));
        }
        float ar = Sx[0], ai = Sy[0];
        ar = fmaf(t1w.x, Sx[1], fmaf( t1w.y, Sy[1], ar));
        ai = fmaf(t1w.x, Sy[1], fmaf(-t1w.y, Sx[1], ai));
        ar = fmaf(t2w.x, Sx[2], fmaf( t2w.y, Sy[2], ar));
        ai = fmaf(t2w.x, Sy[2], fmaf(-t2w.y, Sx[2], ai));
        ar = fmaf(t3w.x, Sx[3], fmaf( t3w.y, Sy[3], ar));
        ai = fmaf(t3w.x, Sy[3], fmaf(-t3w.y, Sx[3], ai));
        stT[w * 18 + u] = make_float2(ar, ai);
    }
    __syncthreads();

    // pass 2: row read (8x LDS.128), radix-4 over uu
    {
        float2 zv[16];
        const float4* row = (const float4*)(stT + w * 18);
        #pragma unroll
        for (int m = 0; m < 8; m++) {
            float4 q = row[m];
            zv[2*m]   = make_float2(q.x, q.y);
            zv[2*m+1] = make_float2(q.z, q.w);
        }
        float Sx[4], Sy[4];
        #pragma unroll
        for (int r = 0; r < 4; r++) {
            float2 z0 = zv[r], z1 = zv[r+4], z2 = zv[r+8], z3 = zv[r+12];
            float Px = fmaf(eu, z2.x, z0.x), Py = fmaf(eu, z2.y, z0.y);
            float Qx = fmaf(eu, z3.x, z1.x), Qy = fmaf(eu, z3.y, z1.y);
            Sx[r] = fmaf(jru, Qx, fmaf(-jiu, Qy, Px));
            Sy[r] = fmaf(jru, Qy, fmaf( jiu, Qx, Py));
        }
        float br = Sx[0], bi = Sy[0];
        br = fmaf(t1u.x, Sx[1], fmaf( t1u.y, Sy[1], br));
        bi = fmaf(t1u.x, Sy[1], fmaf(-t1u.y, Sx[1], bi));
        br = fmaf(t2u.x, Sx[2], fmaf( t2u.y, Sy[2], br));
        bi = fmaf(t2u.x, Sy[2], fmaf(-t2u.y, Sx[2], bi));
        br = fmaf(t3u.x, Sx[3], fmaf( t3u.y, Sy[3], br));
        bi = fmaf(t3u.x, Sy[3], fmaf(-t3u.y, Sx[3], bi));
        zz[tid] = make_float2(br, bi);
    }
    __syncthreads();

    // Hermitian unpack: X1 = (Z(w)+conj Z(-w))/2, X2 = -i(Z(w)-conj Z(-w))/2
    const int co = conj_om(tid);
    if (tid <= co) {
        float2 A = zz[tid], B = zz[co];
        float x1r = 0.5f * (A.x + B.x);
        float x1i = 0.5f * (A.y - B.y);
        float x2r = 0.5f * (A.y + B.y);
        float x2i = 0.5f * (B.x - A.x);
        *reinterpret_cast<float4*>(outh + (size_t)tid * ostride + t0) =
            make_float4(x1r, x1i, x2r, x2i);
    }
}

// ---------------------------------------------------------------------------
// Kernel 2: contraction, f-split halves -> 512 blocks (272 busy), canonical
// omegas only, conjugate partner written for free.
// ---------------------------------------------------------------------------
__global__ __launch_bounds__(256)
void contract_kernel()
{
    const int om    = blockIdx.x & (S - 1);
    const int fhalf = blockIdx.x >> 8;            // 0 or 1
    const int co    = conj_om(om);
    if (om > co) return;

    const int tid = threadIdx.x;

    __shared__ float2 xh[NB * NI];                // [b][i]       4096 B
    __shared__ float2 kh[NI * 32];                // [i][f'] 32x32 8192 B
    const int f0 = fhalf * 32;

    #pragma unroll
    for (int p = 0; p < 2; p++)
        xh[p * 256 + tid] = g_xhat[om * (NB * NI) + p * 256 + tid];
    #pragma unroll
    for (int p = 0; p < 4; p++) {
        int g = p * 256 + tid;                    // 0..1023
        int fl = g >> 5, i = g & 31;
        kh[i * 32 + fl] = g_khat[om * (NF * NI) + (f0 + fl) * NI + i];
    }
    __syncthreads();

    const int fl = tid & 31;
    const int b0 = tid >> 5;                      // 0..7

    float accr[2] = {0.f, 0.f};
    float acci[2] = {0.f, 0.f};

    #pragma unroll 8
    for (int i = 0; i < NI; i++) {
        float2 kv = kh[i * 32 + fl];
        #pragma unroll
        for (int r = 0; r < 2; r++) {
            float2 xv = xh[(b0 + 8 * r) * NI + i];
            accr[r] = fmaf(xv.x, kv.x, fmaf(-xv.y, kv.y, accr[r]));
            acci[r] = fmaf(xv.x, kv.y, fmaf( xv.y, kv.x, acci[r]));
        }
    }

    #pragma unroll
    for (int r = 0; r < 2; r++) {
        int b = b0 + 8 * r;
        g_ohat[om * (NB * NF) + b * NF + f0 + fl] =
            make_float2(accr[r], acci[r]);
        if (om != co)
            g_ohat[co * (NB * NF) + b * NF + f0 + fl] =
                make_float2(accr[r], -acci[r]);
    }
}

// ---------------------------------------------------------------------------
// Kernel 3: inverse 2D FFT + bias, 2-for-1 packed (W = o_f0 + i*o_f1 ->
// IFFT(W) = out_f0 + i*out_f1), radix-4, transposed intermediate.
// ---------------------------------------------------------------------------
__global__ __launch_bounds__(256)
void ifft_kernel(float* __restrict__ out, const float* __restrict__ bias)
{
    const int blk = blockIdx.x;                   // 0..511
    const int b   = blk >> 5;
    const int f0  = (blk & 31) * 2;

    __shared__ float2 sBt[16];
    __shared__ float2 sinb[256];                  // packed W
    __shared__ float2 stT[16 * 18];

    const int tid = threadIdx.x;
    const int u   = tid >> 4;
    const int w   = tid & 15;

    if (tid < 16) sBt[tid] = make_float2(CW16[tid], SW16[tid]);
    {
        float4 z = *reinterpret_cast<const float4*>(
            g_ohat + (size_t)tid * (NB * NF) + b * NF + f0);
        sinb[tid] = make_float2(z.x - z.w, z.y + z.z);   // W = o0 + i*o1
    }
    __syncthreads();

    // inverse twiddles: t'_k = (c, +s); j = (+i)^k
    const float2 j1w = sBt[(4 * w) & 15];
    const float2 t1w = sBt[w], t2w = sBt[(2 * w) & 15], t3w = sBt[(3 * w) & 15];
    const float  ew  = 1.f - 2.f * (float)(w & 1);
    const float  jrw = j1w.x, jiw = j1w.y;

    const float2 j1u = sBt[(4 * u) & 15];
    const float2 t1u = sBt[u], t2u = sBt[(2 * u) & 15], t3u = sBt[(3 * u) & 15];
    const float  eu  = 1.f - 2.f * (float)(u & 1);
    const float  jru = j1u.x, jiu = j1u.y;

    // pass 1 over omega_v; write transposed
    {
        float Sx[4], Sy[4];
        #pragma unroll
        for (int r = 0; r < 4; r++) {
            float2 z0 = sinb[u * 16 + r];
            float2 z1 = sinb[u * 16 + r + 4];
            float2 z2 = sinb[u * 16 + r + 8];
            float2 z3 = sinb[u * 16 + r + 12];
            float Px = fmaf(ew, z2.x, z0.x), Py = fmaf(ew, z2.y, z0.y);
            float Qx = fmaf(ew, z3.x, z1.x), Qy = fmaf(ew, z3.y, z1.y);
            Sx[r] = fmaf(jrw, Qx, fmaf(-jiw, Qy, Px));
            Sy[r] = fmaf(jrw, Qy, fmaf( jiw, Qx, Py));
        }
        float ar = Sx[0], ai = Sy[0];
        ar = fmaf(t1w.x, Sx[1], fmaf(-t1w.y, Sy[1], ar));
        ai = fmaf(t1w.x, Sy[1], fmaf( t1w.y, Sx[1], ai));
        ar = fmaf(t2w.x, Sx[2], fmaf(-t2w.y, Sy[2], ar));
        ai = fmaf(t2w.x, Sy[2], fmaf( t2w.y, Sx[2], ai));
        ar = fmaf(t3w.x, Sx[3], fmaf(-t3w.y, Sy[3], ar));
        ai = fmaf(t3w.x, Sy[3], fmaf( t3w.y, Sx[3], ai));
        stT[w * 18 + u] = make_float2(ar, ai);
    }
    __syncthreads();

    // pass 2 over omega_u: row read; Re -> f0, Im -> f0+1
    {
        float2 zv[16];
        const float4* row = (const float4*)(stT + w * 18);
        #pragma unroll
        for (int m = 0; m < 8; m++) {
            float4 q = row[m];
            zv[2*m]   = make_float2(q.x, q.y);
            zv[2*m+1] = make_float2(q.z, q.w);
        }
        float Sx[4], Sy[4];
        #pragma unroll
        for (int r = 0; r < 4; r++) {
            float2 z0 = zv[r], z1 = zv[r+4], z2 = zv[r+8], z3 = zv[r+12];
            float Px = fmaf(eu, z2.x, z0.x), Py = fmaf(eu, z2.y, z0.y);
            float Qx = fmaf(eu, z3.x, z1.x), Qy = fmaf(eu, z3.y, z1.y);
            Sx[r] = fmaf(jru, Qx, fmaf(-jiu, Qy, Px));
            Sy[r] = fmaf(jru, Qy, fmaf( jiu, Qx, Py));
        }
        float br = Sx[0], bi = Sy[0];
        br = fmaf(t1u.x, Sx[1], fmaf(-t1u.y, Sy[1], br));
        bi = fmaf(t1u.x, Sy[1], fmaf( t1u.y, Sx[1], bi));
        br = fmaf(t2u.x, Sx[2], fmaf(-t2u.y, Sy[2], br));
        bi = fmaf(t2u.x, Sy[2], fmaf( t2u.y, Sx[2], bi));
        br = fmaf(t3u.x, Sx[3], fmaf(-t3u.y, Sy[3], br));
        bi = fmaf(t3u.x, Sy[3], fmaf( t3u.y, Sx[3], bi));

        float* o = out + b * (NF * S) + f0 * S + tid;
        o[0] = br * (1.0f / 256.0f) + bias[f0];
        o[S] = bi * (1.0f / 256.0f) + bias[f0 + 1];
    }
}

// ---------------------------------------------------------------------------
extern "C" void kernel_launch(void* const* d_in, const int* in_sizes, int n_in,
                              void* d_out, int out_size) {
    const float* x    = (const float*)d_in[0];   // (16, 32, 256)
    const float* kern = (const float*)d_in[1];   // (64, 32, 256)
    const float* bias = (const float*)d_in[2];   // (64,)
    // d_in[3] = product_table of the 2D translation group (deterministic);
    // exploited analytically via the convolution theorem.
    float* out = (float*)d_out;                  // (16, 64, 256)

    fft_fwd_all<<<(NB * NI + NF * NI) / 2, 256>>>(x, kern);
    contract_kernel<<<2 * S, 256>>>();
    ifft_kernel<<<(NB * NF) / 2, 256>>>(out, bias);
}

// round 16
// speedup vs baseline: 1.0428x; 1.0428x over previous
#include <cuda_runtime.h>

// Problem constants
#define S    256   // n_symm = 16 x 16 torus
#define NI   32    // in_features
#define NF   64    // features
#define NB   16    // batch

__constant__ float CW16[16] = {
    1.0f,  0.9238795325112867f,  0.7071067811865476f,  0.3826834323650898f,
    0.0f, -0.3826834323650898f, -0.7071067811865476f, -0.9238795325112867f,
   -1.0f, -0.9238795325112867f, -0.7071067811865476f, -0.3826834323650898f,
    0.0f,  0.3826834323650898f,  0.7071067811865476f,  0.9238795325112867f
};
__constant__ float SW16[16] = {
    0.0f,  0.3826834323650898f,  0.7071067811865476f,  0.9238795325112867f,
    1.0f,  0.9238795325112867f,  0.7071067811865476f,  0.3826834323650898f,
    0.0f, -0.3826834323650898f, -0.7071067811865476f, -0.9238795325112867f,
   -1.0f, -0.9238795325112867f, -0.7071067811865476f, -0.3826834323650898f
};

__device__ __align__(16) float2 g_xhat[S * NB * NI];   // [omega][b*32+i]
__device__ __align__(16) float2 g_khat[S * NF * NI];   // [omega][f*32+i]
__device__ __align__(16) float2 g_ohat[S * NB * NF];   // [omega][b*64+f]

__device__ __forceinline__ int conj_om(int om) {
    int u = om >> 4, w = om & 15;
    return (((16 - u) & 15) << 4) | ((16 - w) & 15);
}

// ---------------------------------------------------------------------------
// Kernel 1: forward 2D FFT (16x16), 2-for-1 real packed, radix-4,
// transposed pass-1 intermediate. Grid 1280. Triggers PDL for contract.
// ---------------------------------------------------------------------------
__global__ __launch_bounds__(256)
void fft_fwd_all(const float* __restrict__ x, const float* __restrict__ kern)
{
    const int pb = blockIdx.x;
    const float* in; float2* outh; int ostride, t0;
    if (pb < (NB * NI) / 2) {
        in = x;    outh = g_xhat; ostride = NB * NI; t0 = pb * 2;
    } else {
        in = kern; outh = g_khat; ostride = NF * NI;
        t0 = (pb - (NB * NI) / 2) * 2;
    }

    __shared__ float  sr[512];             // tile0 (re), tile1 (im)
    __shared__ float2 sBt[16];
    __shared__ float2 stT[16 * 18];        // pass-1 result, TRANSPOSED [w][u]
    __shared__ float2 zz[256];             // pass-2 result (for unpack)

    const int tid = threadIdx.x;
    const int u   = tid >> 4;
    const int w   = tid & 15;

    if (tid < 16) sBt[tid] = make_float2(CW16[tid], SW16[tid]);
    ((float2*)sr)[tid] = ((const float2*)(in + t0 * 256))[tid];
    __syncthreads();

    // forward twiddles: t_k = (c, -s); j = (-i)^k
    const float2 j1w = sBt[(4 * w) & 15];
    const float2 t1w = sBt[w], t2w = sBt[(2 * w) & 15], t3w = sBt[(3 * w) & 15];
    const float  ew  = 1.f - 2.f * (float)(w & 1);
    const float  jrw = j1w.x, jiw = -j1w.y;

    const float2 j1u = sBt[(4 * u) & 15];
    const float2 t1u = sBt[u], t2u = sBt[(2 * u) & 15], t3u = sBt[(3 * u) & 15];
    const float  eu  = 1.f - 2.f * (float)(u & 1);
    const float  jru = j1u.x, jiu = -j1u.y;

    // pass 1: z[v] = (tile0[u][v], tile1[u][v]); write transposed
    {
        float zr[16], zi[16];
        const float4* r4 = (const float4*)(sr + u * 16);
        const float4* i4 = (const float4*)(sr + 256 + u * 16);
        #pragma unroll
        for (int q = 0; q < 4; q++) {
            float4 a = r4[q], b = i4[q];
            zr[q*4+0]=a.x; zr[q*4+1]=a.y; zr[q*4+2]=a.z; zr[q*4+3]=a.w;
            zi[q*4+0]=b.x; zi[q*4+1]=b.y; zi[q*4+2]=b.z; zi[q*4+3]=b.w;
        }
        float Sx[4], Sy[4];
        #pragma unroll
        for (int r = 0; r < 4; r++) {
            float Px = fmaf(ew, zr[r + 8],  zr[r]);
            float Py = fmaf(ew, zi[r + 8],  zi[r]);
            float Qx = fmaf(ew, zr[r + 12], zr[r + 4]);
            float Qy = fmaf(ew, zi[r + 12], zi[r + 4]);
            Sx[r] = fmaf(jrw, Qx, fmaf(-jiw, Qy, Px));
            Sy[r] = fmaf(jrw, Qy, fmaf( jiw, Qx, Py));
        }
        float ar = Sx[0], ai = Sy[0];
        ar = fmaf(t1w.x, Sx[1], fmaf( t1w.y, Sy[1], ar));
        ai = fmaf(t1w.x, Sy[1], fmaf(-t1w.y, Sx[1], ai));
        ar = fmaf(t2w.x, Sx[2], fmaf( t2w.y, Sy[2], ar));
        ai = fmaf(t2w.x, Sy[2], fmaf(-t2w.y, Sx[2], ai));
        ar = fmaf(t3w.x, Sx[3], fmaf( t3w.y, Sy[3], ar));
        ai = fmaf(t3w.x, Sy[3], fmaf(-t3w.y, Sx[3], ai));
        stT[w * 18 + u] = make_float2(ar, ai);
    }
    __syncthreads();

    // pass 2: row read (8x LDS.128), radix-4 over uu
    {
        float2 zv[16];
        const float4* row = (const float4*)(stT + w * 18);
        #pragma unroll
        for (int m = 0; m < 8; m++) {
            float4 q = row[m];
            zv[2*m]   = make_float2(q.x, q.y);
            zv[2*m+1] = make_float2(q.z, q.w);
        }
        float Sx[4], Sy[4];
        #pragma unroll
        for (int r = 0; r < 4; r++) {
            float2 z0 = zv[r], z1 = zv[r+4], z2 = zv[r+8], z3 = zv[r+12];
            float Px = fmaf(eu, z2.x, z0.x), Py = fmaf(eu, z2.y, z0.y);
            float Qx = fmaf(eu, z3.x, z1.x), Qy = fmaf(eu, z3.y, z1.y);
            Sx[r] = fmaf(jru, Qx, fmaf(-jiu, Qy, Px));
            Sy[r] = fmaf(jru, Qy, fmaf( jiu, Qx, Py));
        }
        float br = Sx[0], bi = Sy[0];
        br = fmaf(t1u.x, Sx[1], fmaf( t1u.y, Sy[1], br));
        bi = fmaf(t1u.x, Sy[1], fmaf(-t1u.y, Sx[1], bi));
        br = fmaf(t2u.x, Sx[2], fmaf( t2u.y, Sy[2], br));
        bi = fmaf(t2u.x, Sy[2], fmaf(-t2u.y, Sx[2], bi));
        br = fmaf(t3u.x, Sx[3], fmaf( t3u.y, Sy[3], br));
        bi = fmaf(t3u.x, Sy[3], fmaf(-t3u.y, Sx[3], bi));
        zz[tid] = make_float2(br, bi);
    }
    __syncthreads();

    // Hermitian unpack: X1 = (Z(w)+conj Z(-w))/2, X2 = -i(Z(w)-conj Z(-w))/2
    const int co = conj_om(tid);
    if (tid <= co) {
        float2 A = zz[tid], B = zz[co];
        float x1r = 0.5f * (A.x + B.x);
        float x1i = 0.5f * (A.y - B.y);
        float x2r = 0.5f * (A.y + B.y);
        float x2i = 0.5f * (B.x - A.x);
        *reinterpret_cast<float4*>(outh + (size_t)tid * ostride + t0) =
            make_float4(x1r, x1i, x2r, x2i);
    }
    // allow the dependent (contract) grid to be scheduled while we drain;
    // its cudaGridDependencySynchronize() provides the memory fence.
    cudaTriggerProgrammaticLaunchCompletion();
}

// ---------------------------------------------------------------------------
// Kernel 2: contraction, f-split halves -> 512 blocks (272 busy). PDL
// dependent of fft; PDL producer for ifft.
// ---------------------------------------------------------------------------
__global__ __launch_bounds__(256)
void contract_kernel()
{
    const int om    = blockIdx.x & (S - 1);
    const int fhalf = blockIdx.x >> 8;            // 0 or 1
    const int co    = conj_om(om);
    if (om > co) return;                          // exit counts as trigger

    const int tid = threadIdx.x;

    __shared__ float2 xh[NB * NI];                // [b][i]       4096 B
    __shared__ float2 kh[NI * 32];                // [i][f'] 32x32 8192 B
    const int f0 = fhalf * 32;

    // wait for fft's writes to be visible, then load
    cudaGridDependencySynchronize();

    #pragma unroll
    for (int p = 0; p < 2; p++)
        xh[p * 256 + tid] = g_xhat[om * (NB * NI) + p * 256 + tid];
    #pragma unroll
    for (int p = 0; p < 4; p++) {
        int g = p * 256 + tid;                    // 0..1023
        int fl = g >> 5, i = g & 31;
        kh[i * 32 + fl] = g_khat[om * (NF * NI) + (f0 + fl) * NI + i];
    }
    __syncthreads();

    const int fl = tid & 31;
    const int b0 = tid >> 5;                      // 0..7

    float accr[2] = {0.f, 0.f};
    float acci[2] = {0.f, 0.f};

    #pragma unroll 8
    for (int i = 0; i < NI; i++) {
        float2 kv = kh[i * 32 + fl];
        #pragma unroll
        for (int r = 0; r < 2; r++) {
            float2 xv = xh[(b0 + 8 * r) * NI + i];
            accr[r] = fmaf(xv.x, kv.x, fmaf(-xv.y, kv.y, accr[r]));
            acci[r] = fmaf(xv.x, kv.y, fmaf( xv.y, kv.x, acci[r]));
        }
    }

    #pragma unroll
    for (int r = 0; r < 2; r++) {
        int b = b0 + 8 * r;
        g_ohat[om * (NB * NF) + b * NF + f0 + fl] =
            make_float2(accr[r], acci[r]);
        if (om != co)
            g_ohat[co * (NB * NF) + b * NF + f0 + fl] =
                make_float2(accr[r], -acci[r]);
    }
    cudaTriggerProgrammaticLaunchCompletion();
}

// ---------------------------------------------------------------------------
// Kernel 3: inverse 2D FFT + bias, 2-for-1 packed. PDL dependent of contract;
// twiddle/bias preamble runs before the dependency sync.
// ---------------------------------------------------------------------------
__global__ __launch_bounds__(256)
void ifft_kernel(float* __restrict__ out, const float* __restrict__ bias)
{
    const int blk = blockIdx.x;                   // 0..511
    const int b   = blk >> 5;
    const int f0  = (blk & 31) * 2;

    __shared__ float2 sBt[16];
    __shared__ float2 sinb[256];                  // packed W
    __shared__ float2 stT[16 * 18];

    const int tid = threadIdx.x;
    const int u   = tid >> 4;
    const int w   = tid & 15;

    // producer-independent preamble (overlaps contract's tail under PDL)
    if (tid < 16) sBt[tid] = make_float2(CW16[tid], SW16[tid]);
    const float bias0 = bias[f0];
    const float bias1 = bias[f0 + 1];
    __syncthreads();

    // inverse twiddles: t'_k = (c, +s); j = (+i)^k
    const float2 j1w = sBt[(4 * w) & 15];
    const float2 t1w = sBt[w], t2w = sBt[(2 * w) & 15], t3w = sBt[(3 * w) & 15];
    const float  ew  = 1.f - 2.f * (float)(w & 1);
    const float  jrw = j1w.x, jiw = j1w.y;

    const float2 j1u = sBt[(4 * u) & 15];
    const float2 t1u = sBt[u], t2u = sBt[(2 * u) & 15], t3u = sBt[(3 * u) & 15];
    const float  eu  = 1.f - 2.f * (float)(u & 1);
    const float  jru = j1u.x, jiu = j1u.y;

    // wait for contract's g_ohat writes, then load packed spectrum
    cudaGridDependencySynchronize();
    {
        float4 z = *reinterpret_cast<const float4*>(
            g_ohat + (size_t)tid * (NB * NF) + b * NF + f0);
        sinb[tid] = make_float2(z.x - z.w, z.y + z.z);   // W = o0 + i*o1
    }
    __syncthreads();

    // pass 1 over omega_v; write transposed
    {
        float Sx[4], Sy[4];
        #pragma unroll
        for (int r = 0; r < 4; r++) {
            float2 z0 = sinb[u * 16 + r];
            float2 z1 = sinb[u * 16 + r + 4];
            float2 z2 = sinb[u * 16 + r + 8];
            float2 z3 = sinb[u * 16 + r + 12];
            float Px = fmaf(ew, z2.x, z0.x), Py = fmaf(ew, z2.y, z0.y);
            float Qx = fmaf(ew, z3.x, z1.x), Qy = fmaf(ew, z3.y, z1.y);
            Sx[r] = fmaf(jrw, Qx, fmaf(-jiw, Qy, Px));
            Sy[r] = fmaf(jrw, Qy, fmaf( jiw, Qx, Py));
        }
        float ar = Sx[0], ai = Sy[0];
        ar = fmaf(t1w.x, Sx[1], fmaf(-t1w.y, Sy[1], ar));
        ai = fmaf(t1w.x, Sy[1], fmaf( t1w.y, Sx[1], ai));
        ar = fmaf(t2w.x, Sx[2], fmaf(-t2w.y, Sy[2], ar));
        ai = fmaf(t2w.x, Sy[2], fmaf( t2w.y, Sx[2], ai));
        ar = fmaf(t3w.x, Sx[3], fmaf(-t3w.y, Sy[3], ar));
        ai = fmaf(t3w.x, Sy[3], fmaf( t3w.y, Sx[3], ai));
        stT[w * 18 + u] = make_float2(ar, ai);
    }
    __syncthreads();

    // pass 2 over omega_u: row read; Re -> f0, Im -> f0+1
    {
        float2 zv[16];
        const float4* row = (const float4*)(stT + w * 18);
        #pragma unroll
        for (int m = 0; m < 8; m++) {
            float4 q = row[m];
            zv[2*m]   = make_float2(q.x, q.y);
            zv[2*m+1] = make_float2(q.z, q.w);
        }
        float Sx[4], Sy[4];
        #pragma unroll
        for (int r = 0; r < 4; r++) {
            float2 z0 = zv[r], z1 = zv[r+4], z2 = zv[r+8], z3 = zv[r+12];
            float Px = fmaf(eu, z2.x, z0.x), Py = fmaf(eu, z2.y, z0.y);
            float Qx = fmaf(eu, z3.x, z1.x), Qy = fmaf(eu, z3.y, z1.y);
            Sx[r] = fmaf(jru, Qx, fmaf(-jiu, Qy, Px));
            Sy[r] = fmaf(jru, Qy, fmaf( jiu, Qx, Py));
        }
        float br = Sx[0], bi = Sy[0];
        br = fmaf(t1u.x, Sx[1], fmaf(-t1u.y, Sy[1], br));
        bi = fmaf(t1u.x, Sy[1], fmaf( t1u.y, Sx[1], bi));
        br = fmaf(t2u.x, Sx[2], fmaf(-t2u.y, Sy[2], br));
        bi = fmaf(t2u.x, Sy[2], fmaf( t2u.y, Sx[2], bi));
        br = fmaf(t3u.x, Sx[3], fmaf(-t3u.y, Sy[3], br));
        bi = fmaf(t3u.x, Sy[3], fmaf( t3u.y, Sx[3], bi));

        float* o = out + b * (NF * S) + f0 * S + tid;
        o[0] = br * (1.0f / 256.0f) + bias0;
        o[S] = bi * (1.0f / 256.0f) + bias1;
    }
}

// ---------------------------------------------------------------------------
extern "C" void kernel_launch(void* const* d_in, const int* in_sizes, int n_in,
                              void* d_out, int out_size) {
    const float* x    = (const float*)d_in[0];   // (16, 32, 256)
    const float* kern = (const float*)d_in[1];   // (64, 32, 256)
    const float* bias = (const float*)d_in[2];   // (64,)
    // d_in[3] = product_table of the 2D translation group (deterministic);
    // exploited analytically via the convolution theorem.
    float* out = (float*)d_out;                  // (16, 64, 256)

    fft_fwd_all<<<(NB * NI + NF * NI) / 2, 256>>>(x, kern);

    // PDL: contract + ifft serialize programmatically with the previous
    // kernel in the stream (graph capture records programmatic edges).
    cudaLaunchAttribute attr[1];
    attr[0].id = cudaLaunchAttributeProgrammaticStreamSerialization;
    attr[0].val.programmaticStreamSerializationAllowed = 1;

    {
        cudaLaunchConfig_t cfg = {};
        cfg.gridDim  = dim3(2 * S);
        cfg.blockDim = dim3(256);
        cfg.attrs    = attr;
        cfg.numAttrs = 1;
        cfg.stream   = 0;
        cudaLaunchKernelEx(&cfg, contract_kernel);
    }
    {
        cudaLaunchConfig_t cfg = {};
        cfg.gridDim  = dim3((NB * NF) / 2);
        cfg.blockDim = dim3(256);
        cfg.attrs    = attr;
        cfg.numAttrs = 1;
        cfg.stream   = 0;
        cudaLaunchKernelEx(&cfg, ifft_kernel, (float*)d_out, bias);
    }
}